// round 7
// baseline (speedup 1.0000x reference)
#include <cuda_runtime.h>
#include <math.h>

#define Hh 512
#define Ww 512
#define NPIX (512*512)
#define KK 50
#define BB 16
#define SLIC_ITERS 10

// scratch (static device arrays; no dynamic allocation allowed)
__device__ double        g_accum[BB][KK][6];     // [0..4]=feat sums, [5]=count
__device__ float         g_centers[BB][KK][5];
__device__ unsigned char g_labels[BB][NPIX];
__device__ double        g_colorsum[BB][3];

__device__ __forceinline__ float ratio_f() {
    return (float)(10.0 / sqrt((double)NPIX / (double)KK));
}

// ---------------------------------------------------------------------------
// init: zero accumulators + grid-initialized centers (first 50 of 8x8 grid)
// ---------------------------------------------------------------------------
__global__ void init_kernel(const float* __restrict__ x) {
    int b = blockIdx.x;
    int tid = threadIdx.x;
    if (tid < KK * 6) ((double*)g_accum[b])[tid] = 0.0;
    if (b == 0 && tid >= 448 && tid < 448 + BB * 3) ((double*)g_colorsum)[tid - 448] = 0.0;
    if (tid < KK) {
        int i = tid >> 3, j = tid & 7;
        int y = 32 + 64 * i;
        int xc = 32 + 64 * j;
        const float* xb = x + (size_t)b * 3 * NPIX;
        float r  = xb[y * Ww + xc];
        float g  = xb[NPIX + y * Ww + xc];
        float bl = xb[2 * NPIX + y * Ww + xc];
        float fr = ratio_f();
        g_centers[b][tid][0] = r;
        g_centers[b][tid][1] = g;
        g_centers[b][tid][2] = bl;
        g_centers[b][tid][3] = __fmul_rn((float)y, fr);
        g_centers[b][tid][4] = __fmul_rn((float)xc, fr);
    }
}

// ---------------------------------------------------------------------------
// assign + accumulate segment sums.
// Block = 64x32 pixel tile; 1 thread = 4x2 pixel patch (16x16 patches).
// (8 px/thread keeps regs ~75 -> 3 CTAs/SM @ launch_bounds(256,3); the
//  16-px version sat at the 128-reg cap and likely spilled dmin/lab to local.)
// Exact spatial pruning (labels bit-identical): candidate iff
//   spatialMin2_j <= min_j'(spatialMax2_j') + 3 (color slack) [+ fp pad]
// Candidates compacted ascending-j; +INF sentinel padding; fixed 16-candidate
// unrolled rounds.  d_j = ||c_j||^2 - 2 f.c_j  (f^2 dropped, argmin-safe)
// Accumulation: fp32 run partials -> native global f64 L2 red atomics.
// ---------------------------------------------------------------------------
__global__ __launch_bounds__(256, 3) void assign_kernel(const float* __restrict__ x,
                                                        int storeLabels) {
    __shared__ float4 s_candA[64];            // {-2c0,-2c1,-2c2,-2c3}
    __shared__ float2 s_candB[64];            // {-2c4, ||c||^2 or +INF sentinel}
    __shared__ unsigned char s_jidx[64];
    __shared__ float s_smax[64];
    __shared__ unsigned int s_mask[2];
    __shared__ float s_T;

    int b   = blockIdx.y;
    int tid = threadIdx.x;
    int tileX = (blockIdx.x & 7) << 6;        // 8 x-tiles of 64
    int tileY = (blockIdx.x >> 3) << 5;       // 16 y-tiles of 32

    float fr = ratio_f();
    float byLo = __fmul_rn((float)tileY, fr);
    float byHi = __fmul_rn((float)(tileY + 31), fr);
    float bxLo = __fmul_rn((float)tileX, fr);
    float bxHi = __fmul_rn((float)(tileX + 63), fr);

    float c0 = 0.f, c1 = 0.f, c2 = 0.f, c3 = 0.f, c4 = 0.f, smin = 0.f;
    if (tid < 64) {
        s_candA[tid] = make_float4(0.f, 0.f, 0.f, 0.f);
        s_candB[tid] = make_float2(0.f, __int_as_float(0x7f800000));  // +INF
        s_jidx[tid] = 0;
        s_smax[tid] = 3.4e38f;
    }
    if (tid < KK) {
        c0 = g_centers[b][tid][0];
        c1 = g_centers[b][tid][1];
        c2 = g_centers[b][tid][2];
        c3 = g_centers[b][tid][3];
        c4 = g_centers[b][tid][4];
        float dyo = fmaxf(fmaxf(byLo - c3, c3 - byHi), 0.0f);
        float dxo = fmaxf(fmaxf(bxLo - c4, c4 - bxHi), 0.0f);
        smin = dyo * dyo + dxo * dxo;
        float dyM = fmaxf(fabsf(c3 - byLo), fabsf(c3 - byHi));
        float dxM = fmaxf(fabsf(c4 - bxLo), fabsf(c4 - bxHi));
        s_smax[tid] = dyM * dyM + dxM * dxM;
    }
    __syncthreads();
    if (tid < 32) {                        // warp-parallel min reduction
        float v = fminf(s_smax[tid], s_smax[tid + 32]);
#pragma unroll
        for (int off = 16; off > 0; off >>= 1)
            v = fminf(v, __shfl_xor_sync(0xffffffffu, v, off));
        if (tid == 0) s_T = v + 3.0f + 1e-3f;  // color slack + fp pad
    }
    __syncthreads();
    bool keep = (tid < KK) && (smin <= s_T);
    unsigned int wm = __ballot_sync(0xffffffffu, keep);
    if (tid < 64 && (tid & 31) == 0) s_mask[tid >> 5] = wm;
    __syncthreads();
    unsigned int m0 = s_mask[0], m1 = s_mask[1];
    if (keep) {
        unsigned int mm = (tid < 32) ? m0 : m1;
        int base = (tid < 32) ? 0 : __popc(m0);
        int pos = base + __popc(mm & ((1u << (tid & 31)) - 1u));
        float cc = __fmul_rn(c0, c0);
        cc = __fmaf_rn(c1, c1, cc);
        cc = __fmaf_rn(c2, c2, cc);
        cc = __fmaf_rn(c3, c3, cc);
        cc = __fmaf_rn(c4, c4, cc);
        s_candA[pos] = make_float4(__fmul_rn(-2.0f, c0), __fmul_rn(-2.0f, c1),
                                   __fmul_rn(-2.0f, c2), __fmul_rn(-2.0f, c3));
        s_candB[pos] = make_float2(__fmul_rn(-2.0f, c4), cc);
        s_jidx[pos] = (unsigned char)tid;
    }
    int C = __popc(m0) + __popc(m1);
    __syncthreads();

    int y0 = tileY + ((tid >> 4) << 1);       // 16 y-patches of 2 rows
    int x0 = tileX + ((tid & 15) << 2);       // 16 x-patches of 4 cols

    const float* xr = x + (size_t)b * 3 * NPIX;
    const float* xg = xr + NPIX;
    const float* xb = xr + 2 * NPIX;

    float fxc[4], fy[2];
#pragma unroll
    for (int i = 0; i < 4; i++) fxc[i] = __fmul_rn((float)(x0 + i), fr);
#pragma unroll
    for (int i = 0; i < 2; i++) fy[i] = __fmul_rn((float)(y0 + i), fr);

    // load the 4x2 patch (3 channels)
    float4 Rr[2], Gr[2], Br[2];
#pragma unroll
    for (int r = 0; r < 2; r++) {
        Rr[r] = *(const float4*)(xr + (y0 + r) * Ww + x0);
        Gr[r] = *(const float4*)(xg + (y0 + r) * Ww + x0);
        Br[r] = *(const float4*)(xb + (y0 + r) * Ww + x0);
    }

    float dmin[8];
    int   lab[8];
#pragma unroll
    for (int p = 0; p < 8; p++) { dmin[p] = 3.4e38f; lab[p] = 0; }

    // fixed-trip unrolled rounds of 16 candidates (sentinel-padded, exact)
    int rounds = (C + 15) >> 4;            // 1 typically
    for (int rd = 0; rd < rounds; rd++) {
        int cbase = rd << 4;
#pragma unroll
        for (int i = 0; i < 16; i++) {
            int c = cbase + i;
            float4 cA = s_candA[c];
            float2 cB = s_candB[c];
            float e0 = __fmaf_rn(cA.w, fy[0], cB.y);
            float e1 = __fmaf_rn(cA.w, fy[1], cB.y);
#pragma unroll
            for (int r = 0; r < 2; r++) {
                float er = (r == 0) ? e0 : e1;
                const float* Rp = (const float*)&Rr[r];
                const float* Gp = (const float*)&Gr[r];
                const float* Bp = (const float*)&Br[r];
#pragma unroll
                for (int q = 0; q < 4; q++) {
                    float d = __fmaf_rn(cB.x, fxc[q], er);
                    d = __fmaf_rn(cA.x, Rp[q], d);
                    d = __fmaf_rn(cA.y, Gp[q], d);
                    d = __fmaf_rn(cA.z, Bp[q], d);
                    int p = r * 4 + q;
                    if (d < dmin[p]) { dmin[p] = d; lab[p] = c; }
                }
            }
        }
    }

    // accumulate per-thread run partials in FP32, flush -> native f64 L2 red
    double* gacc = (double*)g_accum[b];
    int curLab = -1;
    float a0 = 0.f, a1 = 0.f, a2 = 0.f, a3 = 0.f, a4 = 0.f, a5 = 0.f;
#pragma unroll
    for (int p = 0; p < 8; p++) {
        int r = p >> 2, q = p & 3;
        int l = lab[p];
        if (l != curLab) {
            if (curLab >= 0) {
                int jj = s_jidx[curLab];
                atomicAdd(&gacc[jj * 6 + 0], (double)a1);
                atomicAdd(&gacc[jj * 6 + 1], (double)a2);
                atomicAdd(&gacc[jj * 6 + 2], (double)a3);
                atomicAdd(&gacc[jj * 6 + 3], (double)a4);
                atomicAdd(&gacc[jj * 6 + 4], (double)a5);
                atomicAdd(&gacc[jj * 6 + 5], (double)a0);
            }
            curLab = l;
            a0 = a1 = a2 = a3 = a4 = a5 = 0.f;
        }
        a0 += 1.0f;
        a1 += ((const float*)&Rr[r])[q];
        a2 += ((const float*)&Gr[r])[q];
        a3 += ((const float*)&Br[r])[q];
        a4 += fy[r];
        a5 += fxc[q];
    }
    if (curLab >= 0) {
        int jj = s_jidx[curLab];
        atomicAdd(&gacc[jj * 6 + 0], (double)a1);
        atomicAdd(&gacc[jj * 6 + 1], (double)a2);
        atomicAdd(&gacc[jj * 6 + 2], (double)a3);
        atomicAdd(&gacc[jj * 6 + 3], (double)a4);
        atomicAdd(&gacc[jj * 6 + 4], (double)a5);
        atomicAdd(&gacc[jj * 6 + 5], (double)a0);
    }

    if (storeLabels) {
#pragma unroll
        for (int r = 0; r < 2; r++) {
            uchar4 L4 = make_uchar4(s_jidx[lab[r * 4 + 0]], s_jidx[lab[r * 4 + 1]],
                                    s_jidx[lab[r * 4 + 2]], s_jidx[lab[r * 4 + 3]]);
            *(uchar4*)&g_labels[b][(y0 + r) * Ww + x0] = L4;
        }
    }
}

// ---------------------------------------------------------------------------
// centers <- sums / max(cnt,1); zero accumulator for next pass
// ---------------------------------------------------------------------------
__global__ void update_kernel() {
    int b = blockIdx.x;
    int k = threadIdx.x;
    if (k < KK) {
        double* a = g_accum[b][k];
        double cnt = a[5];
        double dv = cnt > 1.0 ? cnt : 1.0;
#pragma unroll
        for (int c = 0; c < 5; c++) {
            g_centers[b][k][c] = (float)(a[c] / dv);
            a[c] = 0.0;
        }
        a[5] = 0.0;
    }
}

// ---------------------------------------------------------------------------
// weighted color sum: w = 1/max(cnt,1) (fp32, like JAX); per-thread fp32
// partial (4 products), widened to double in the warp reduction + atomic
// ---------------------------------------------------------------------------
__global__ __launch_bounds__(256) void weight_kernel(const float* __restrict__ x) {
    __shared__ float s_inv[KK];
    int b   = blockIdx.y;
    int tid = threadIdx.x;
    if (tid < KK) {
        float cnt = (float)g_accum[b][tid][5];
        cnt = fmaxf(cnt, 1.0f);
        s_inv[tid] = __fdiv_rn(1.0f, cnt);
    }
    __syncthreads();

    int idx = (blockIdx.x * 256 + tid) * 4;
    const float* xr = x + (size_t)b * 3 * NPIX;
    const float* xg = xr + NPIX;
    const float* xb = xr + 2 * NPIX;
    float4 R  = *(const float4*)(xr + idx);
    float4 G  = *(const float4*)(xg + idx);
    float4 Bc = *(const float4*)(xb + idx);
    uchar4 L  = *(const uchar4*)&g_labels[b][idx];

    float w0 = s_inv[L.x], w1 = s_inv[L.y], w2 = s_inv[L.z], w3 = s_inv[L.w];
    float frt = __fadd_rn(__fadd_rn(__fmul_rn(R.x, w0), __fmul_rn(R.y, w1)),
                          __fadd_rn(__fmul_rn(R.z, w2), __fmul_rn(R.w, w3)));
    float fgt = __fadd_rn(__fadd_rn(__fmul_rn(G.x, w0), __fmul_rn(G.y, w1)),
                          __fadd_rn(__fmul_rn(G.z, w2), __fmul_rn(G.w, w3)));
    float fbt = __fadd_rn(__fadd_rn(__fmul_rn(Bc.x, w0), __fmul_rn(Bc.y, w1)),
                          __fadd_rn(__fmul_rn(Bc.z, w2), __fmul_rn(Bc.w, w3)));
    double sr = (double)frt, sg = (double)fgt, sb = (double)fbt;
#pragma unroll
    for (int off = 16; off > 0; off >>= 1) {
        sr += __shfl_down_sync(0xffffffffu, sr, off);
        sg += __shfl_down_sync(0xffffffffu, sg, off);
        sb += __shfl_down_sync(0xffffffffu, sb, off);
    }
    if ((tid & 31) == 0) {
        atomicAdd(&g_colorsum[b][0], sr);
        atomicAdd(&g_colorsum[b][1], sg);
        atomicAdd(&g_colorsum[b][2], sb);
    }
}

// ---------------------------------------------------------------------------
// finalize: fp32 epilogue mirroring the reference formula
// ---------------------------------------------------------------------------
__global__ void finalize_kernel(float* __restrict__ out) {
    int b = threadIdx.x;
    if (b < BB) {
        float mr = (float)(g_colorsum[b][0] / (double)NPIX);
        float mg = (float)(g_colorsum[b][1] / (double)NPIX);
        float mb = (float)(g_colorsum[b][2] / (double)NPIX);
        float drg = __fadd_rn(mr, -mg);
        float drb = __fadd_rn(mr, -mb);
        float dgb = __fadd_rn(mb, -mg);
        float Drg = __fmul_rn(drg, drg);
        float Drb = __fmul_rn(drb, drb);
        float Dgb = __fmul_rn(dgb, dgb);
        float t = __fadd_rn(__fadd_rn(__fmul_rn(Drg, Drg), __fmul_rn(Drb, Drb)),
                            __fmul_rn(Dgb, Dgb));
        out[b] = __fsqrt_rn(t);
    }
}

// ---------------------------------------------------------------------------
extern "C" void kernel_launch(void* const* d_in, const int* in_sizes, int n_in,
                              void* d_out, int out_size) {
    const float* x = (const float*)d_in[0];
    float* out = (float*)d_out;

    init_kernel<<<BB, 512>>>(x);
    for (int it = 0; it < SLIC_ITERS; it++) {
        assign_kernel<<<dim3(128, BB), 256>>>(x, 0);
        update_kernel<<<BB, 64>>>();
    }
    assign_kernel<<<dim3(128, BB), 256>>>(x, 1);      // final assign, store labels + counts
    weight_kernel<<<dim3(256, BB), 256>>>(x);
    finalize_kernel<<<1, 32>>>(out);
}

// round 8
// speedup vs baseline: 1.1610x; 1.1610x over previous
#include <cuda_runtime.h>
#include <math.h>

#define Hh 512
#define Ww 512
#define NPIX (512*512)
#define KK 50
#define BB 16
#define SLIC_ITERS 10

// scratch (static device arrays; no dynamic allocation allowed)
__device__ double        g_accum[BB][KK][6];     // [0..4]=feat sums, [5]=count
__device__ float         g_centers[BB][KK][5];
__device__ unsigned char g_labels[BB][NPIX];
__device__ double        g_colorsum[BB][3];

__device__ __forceinline__ float ratio_f() {
    return (float)(10.0 / sqrt((double)NPIX / (double)KK));
}

// ---------------------------------------------------------------------------
// init: zero accumulators + grid-initialized centers (first 50 of 8x8 grid)
// ---------------------------------------------------------------------------
__global__ void init_kernel(const float* __restrict__ x) {
    int b = blockIdx.x;
    int tid = threadIdx.x;
    if (tid < KK * 6) ((double*)g_accum[b])[tid] = 0.0;
    if (b == 0 && tid >= 448 && tid < 448 + BB * 3) ((double*)g_colorsum)[tid - 448] = 0.0;
    if (tid < KK) {
        int i = tid >> 3, j = tid & 7;
        int y = 32 + 64 * i;
        int xc = 32 + 64 * j;
        const float* xb = x + (size_t)b * 3 * NPIX;
        float r  = xb[y * Ww + xc];
        float g  = xb[NPIX + y * Ww + xc];
        float bl = xb[2 * NPIX + y * Ww + xc];
        float fr = ratio_f();
        g_centers[b][tid][0] = r;
        g_centers[b][tid][1] = g;
        g_centers[b][tid][2] = bl;
        g_centers[b][tid][3] = __fmul_rn((float)y, fr);
        g_centers[b][tid][4] = __fmul_rn((float)xc, fr);
    }
}

// ---------------------------------------------------------------------------
// assign + accumulate segment sums.
// Block = 64x64 pixel tile; 1 thread = 4x4 pixel patch (16x16 patches).
// Exact spatial pruning (labels bit-identical): candidate iff
//   spatialMin2_j <= min_j'(spatialMax2_j') + 3 (color slack) [+ fp pad]
// Candidates compacted ascending-j; +INF sentinel padding; fixed 16-candidate
// unrolled rounds.  d_j = ||c_j||^2 - 2 f.c_j  (f^2 dropped, argmin-safe)
//
// Accumulation (two-stage, both levels NATIVE atomics):
//   registers (fp32 run partials)
//     -> shared fp32 atomicAdd   (ATOMS.ADD.F32, native, 32cyc/warp)
//     -> block-end flush of NONZERO cells to global f64 atomicAdd.
// This cuts global f64 atomic traffic ~100x vs R5-R7 (which serialized
// ~1000 f64 adds per address at the L2 atomic ALU = the real bottleneck).
// Reference does fp32 segment_sum, so a bounded per-tile fp32 partial is
// at least as accurate as JAX.
// ---------------------------------------------------------------------------
__global__ __launch_bounds__(256) void assign_kernel(const float* __restrict__ x,
                                                     int storeLabels) {
    __shared__ float4 s_candA[64];            // {-2c0,-2c1,-2c2,-2c3}
    __shared__ float2 s_candB[64];            // {-2c4, ||c||^2 or +INF sentinel}
    __shared__ unsigned char s_jidx[64];
    __shared__ float s_smax[64];
    __shared__ unsigned int s_mask[2];
    __shared__ float s_T;
    __shared__ float s_facc[KK * 6];          // per-block fp32 segment sums

    int b   = blockIdx.y;
    int tid = threadIdx.x;
    int tileX = (blockIdx.x & 7) << 6;
    int tileY = (blockIdx.x >> 3) << 6;

    float fr = ratio_f();
    float byLo = __fmul_rn((float)tileY, fr);
    float byHi = __fmul_rn((float)(tileY + 63), fr);
    float bxLo = __fmul_rn((float)tileX, fr);
    float bxHi = __fmul_rn((float)(tileX + 63), fr);

    float c0 = 0.f, c1 = 0.f, c2 = 0.f, c3 = 0.f, c4 = 0.f, smin = 0.f;
    if (tid < 64) {
        s_candA[tid] = make_float4(0.f, 0.f, 0.f, 0.f);
        s_candB[tid] = make_float2(0.f, __int_as_float(0x7f800000));  // +INF
        s_jidx[tid] = 0;
        s_smax[tid] = 3.4e38f;
    }
    if (tid < KK) {
        c0 = g_centers[b][tid][0];
        c1 = g_centers[b][tid][1];
        c2 = g_centers[b][tid][2];
        c3 = g_centers[b][tid][3];
        c4 = g_centers[b][tid][4];
        float dyo = fmaxf(fmaxf(byLo - c3, c3 - byHi), 0.0f);
        float dxo = fmaxf(fmaxf(bxLo - c4, c4 - bxHi), 0.0f);
        smin = dyo * dyo + dxo * dxo;
        float dyM = fmaxf(fabsf(c3 - byLo), fabsf(c3 - byHi));
        float dxM = fmaxf(fabsf(c4 - bxLo), fabsf(c4 - bxHi));
        s_smax[tid] = dyM * dyM + dxM * dxM;
    }
    for (int i2 = tid; i2 < KK * 6; i2 += 256) s_facc[i2] = 0.f;
    __syncthreads();
    if (tid < 32) {                        // warp-parallel min reduction
        float v = fminf(s_smax[tid], s_smax[tid + 32]);
#pragma unroll
        for (int off = 16; off > 0; off >>= 1)
            v = fminf(v, __shfl_xor_sync(0xffffffffu, v, off));
        if (tid == 0) s_T = v + 3.0f + 1e-3f;  // color slack + fp pad
    }
    __syncthreads();
    bool keep = (tid < KK) && (smin <= s_T);
    unsigned int wm = __ballot_sync(0xffffffffu, keep);
    if (tid < 64 && (tid & 31) == 0) s_mask[tid >> 5] = wm;
    __syncthreads();
    unsigned int m0 = s_mask[0], m1 = s_mask[1];
    if (keep) {
        unsigned int mm = (tid < 32) ? m0 : m1;
        int base = (tid < 32) ? 0 : __popc(m0);
        int pos = base + __popc(mm & ((1u << (tid & 31)) - 1u));
        float cc = __fmul_rn(c0, c0);
        cc = __fmaf_rn(c1, c1, cc);
        cc = __fmaf_rn(c2, c2, cc);
        cc = __fmaf_rn(c3, c3, cc);
        cc = __fmaf_rn(c4, c4, cc);
        s_candA[pos] = make_float4(__fmul_rn(-2.0f, c0), __fmul_rn(-2.0f, c1),
                                   __fmul_rn(-2.0f, c2), __fmul_rn(-2.0f, c3));
        s_candB[pos] = make_float2(__fmul_rn(-2.0f, c4), cc);
        s_jidx[pos] = (unsigned char)tid;
    }
    int C = __popc(m0) + __popc(m1);
    __syncthreads();

    int y0 = tileY + ((tid >> 4) << 2);
    int x0 = tileX + ((tid & 15) << 2);

    const float* xr = x + (size_t)b * 3 * NPIX;
    const float* xg = xr + NPIX;
    const float* xb = xr + 2 * NPIX;

    float fxc[4], fy[4];
#pragma unroll
    for (int i = 0; i < 4; i++) fxc[i] = __fmul_rn((float)(x0 + i), fr);
#pragma unroll
    for (int i = 0; i < 4; i++) fy[i] = __fmul_rn((float)(y0 + i), fr);

    // load the full 4x4 patch (3 channels)
    float4 Rr[4], Gr[4], Br[4];
#pragma unroll
    for (int r = 0; r < 4; r++) {
        Rr[r] = *(const float4*)(xr + (y0 + r) * Ww + x0);
        Gr[r] = *(const float4*)(xg + (y0 + r) * Ww + x0);
        Br[r] = *(const float4*)(xb + (y0 + r) * Ww + x0);
    }

    float dmin[16];
    int   lab[16];
#pragma unroll
    for (int p = 0; p < 16; p++) { dmin[p] = 3.4e38f; lab[p] = 0; }

    // fixed-trip unrolled rounds of 16 candidates (sentinel-padded, exact)
    int rounds = (C + 15) >> 4;            // 1 typically
    for (int rd = 0; rd < rounds; rd++) {
        int cbase = rd << 4;
#pragma unroll
        for (int i = 0; i < 16; i++) {
            int c = cbase + i;
            float4 cA = s_candA[c];
            float2 cB = s_candB[c];
            float e0 = __fmaf_rn(cA.w, fy[0], cB.y);
            float e1 = __fmaf_rn(cA.w, fy[1], cB.y);
            float e2 = __fmaf_rn(cA.w, fy[2], cB.y);
            float e3 = __fmaf_rn(cA.w, fy[3], cB.y);
#pragma unroll
            for (int r = 0; r < 4; r++) {
                float er = (r == 0) ? e0 : (r == 1) ? e1 : (r == 2) ? e2 : e3;
                const float* Rp = (const float*)&Rr[r];
                const float* Gp = (const float*)&Gr[r];
                const float* Bp = (const float*)&Br[r];
#pragma unroll
                for (int q = 0; q < 4; q++) {
                    float d = __fmaf_rn(cB.x, fxc[q], er);
                    d = __fmaf_rn(cA.x, Rp[q], d);
                    d = __fmaf_rn(cA.y, Gp[q], d);
                    d = __fmaf_rn(cA.z, Bp[q], d);
                    int p = r * 4 + q;
                    if (d < dmin[p]) { dmin[p] = d; lab[p] = c; }
                }
            }
        }
    }

    // run partials (fp32 regs) -> shared fp32 NATIVE atomics
    int curLab = -1;
    float a0 = 0.f, a1 = 0.f, a2 = 0.f, a3 = 0.f, a4 = 0.f, a5 = 0.f;
#pragma unroll
    for (int p = 0; p < 16; p++) {
        int r = p >> 2, q = p & 3;
        int l = lab[p];
        if (l != curLab) {
            if (curLab >= 0) {
                int jj = s_jidx[curLab];
                atomicAdd(&s_facc[jj * 6 + 0], a1);
                atomicAdd(&s_facc[jj * 6 + 1], a2);
                atomicAdd(&s_facc[jj * 6 + 2], a3);
                atomicAdd(&s_facc[jj * 6 + 3], a4);
                atomicAdd(&s_facc[jj * 6 + 4], a5);
                atomicAdd(&s_facc[jj * 6 + 5], a0);
            }
            curLab = l;
            a0 = a1 = a2 = a3 = a4 = a5 = 0.f;
        }
        a0 += 1.0f;
        a1 += ((const float*)&Rr[r])[q];
        a2 += ((const float*)&Gr[r])[q];
        a3 += ((const float*)&Br[r])[q];
        a4 += fy[r];
        a5 += fxc[q];
    }
    if (curLab >= 0) {
        int jj = s_jidx[curLab];
        atomicAdd(&s_facc[jj * 6 + 0], a1);
        atomicAdd(&s_facc[jj * 6 + 1], a2);
        atomicAdd(&s_facc[jj * 6 + 2], a3);
        atomicAdd(&s_facc[jj * 6 + 3], a4);
        atomicAdd(&s_facc[jj * 6 + 4], a5);
        atomicAdd(&s_facc[jj * 6 + 5], a0);
    }

    if (storeLabels) {
#pragma unroll
        for (int r = 0; r < 4; r++) {
            uchar4 L4 = make_uchar4(s_jidx[lab[r * 4 + 0]], s_jidx[lab[r * 4 + 1]],
                                    s_jidx[lab[r * 4 + 2]], s_jidx[lab[r * 4 + 3]]);
            *(uchar4*)&g_labels[b][(y0 + r) * Ww + x0] = L4;
        }
    }

    // block-end flush: only nonzero cells -> global f64 atomics (~30-60/CTA)
    __syncthreads();
    double* gacc = (double*)g_accum[b];
    for (int i2 = tid; i2 < KK * 6; i2 += 256) {
        float v = s_facc[i2];
        if (v != 0.f) atomicAdd(&gacc[i2], (double)v);
    }
}

// ---------------------------------------------------------------------------
// centers <- sums / max(cnt,1); zero accumulator for next pass
// ---------------------------------------------------------------------------
__global__ void update_kernel() {
    int b = blockIdx.x;
    int k = threadIdx.x;
    if (k < KK) {
        double* a = g_accum[b][k];
        double cnt = a[5];
        double dv = cnt > 1.0 ? cnt : 1.0;
#pragma unroll
        for (int c = 0; c < 5; c++) {
            g_centers[b][k][c] = (float)(a[c] / dv);
            a[c] = 0.0;
        }
        a[5] = 0.0;
    }
}

// ---------------------------------------------------------------------------
// weighted color sum: w = 1/max(cnt,1) (fp32, like JAX); per-thread fp32
// partial (4 products), widened to double in the warp reduction + atomic
// ---------------------------------------------------------------------------
__global__ __launch_bounds__(256) void weight_kernel(const float* __restrict__ x) {
    __shared__ float s_inv[KK];
    int b   = blockIdx.y;
    int tid = threadIdx.x;
    if (tid < KK) {
        float cnt = (float)g_accum[b][tid][5];
        cnt = fmaxf(cnt, 1.0f);
        s_inv[tid] = __fdiv_rn(1.0f, cnt);
    }
    __syncthreads();

    int idx = (blockIdx.x * 256 + tid) * 4;
    const float* xr = x + (size_t)b * 3 * NPIX;
    const float* xg = xr + NPIX;
    const float* xb = xr + 2 * NPIX;
    float4 R  = *(const float4*)(xr + idx);
    float4 G  = *(const float4*)(xg + idx);
    float4 Bc = *(const float4*)(xb + idx);
    uchar4 L  = *(const uchar4*)&g_labels[b][idx];

    float w0 = s_inv[L.x], w1 = s_inv[L.y], w2 = s_inv[L.z], w3 = s_inv[L.w];
    float frt = __fadd_rn(__fadd_rn(__fmul_rn(R.x, w0), __fmul_rn(R.y, w1)),
                          __fadd_rn(__fmul_rn(R.z, w2), __fmul_rn(R.w, w3)));
    float fgt = __fadd_rn(__fadd_rn(__fmul_rn(G.x, w0), __fmul_rn(G.y, w1)),
                          __fadd_rn(__fmul_rn(G.z, w2), __fmul_rn(G.w, w3)));
    float fbt = __fadd_rn(__fadd_rn(__fmul_rn(Bc.x, w0), __fmul_rn(Bc.y, w1)),
                          __fadd_rn(__fmul_rn(Bc.z, w2), __fmul_rn(Bc.w, w3)));
    double sr = (double)frt, sg = (double)fgt, sb = (double)fbt;
#pragma unroll
    for (int off = 16; off > 0; off >>= 1) {
        sr += __shfl_down_sync(0xffffffffu, sr, off);
        sg += __shfl_down_sync(0xffffffffu, sg, off);
        sb += __shfl_down_sync(0xffffffffu, sb, off);
    }
    if ((tid & 31) == 0) {
        atomicAdd(&g_colorsum[b][0], sr);
        atomicAdd(&g_colorsum[b][1], sg);
        atomicAdd(&g_colorsum[b][2], sb);
    }
}

// ---------------------------------------------------------------------------
// finalize: fp32 epilogue mirroring the reference formula
// ---------------------------------------------------------------------------
__global__ void finalize_kernel(float* __restrict__ out) {
    int b = threadIdx.x;
    if (b < BB) {
        float mr = (float)(g_colorsum[b][0] / (double)NPIX);
        float mg = (float)(g_colorsum[b][1] / (double)NPIX);
        float mb = (float)(g_colorsum[b][2] / (double)NPIX);
        float drg = __fadd_rn(mr, -mg);
        float drb = __fadd_rn(mr, -mb);
        float dgb = __fadd_rn(mb, -mg);
        float Drg = __fmul_rn(drg, drg);
        float Drb = __fmul_rn(drb, drb);
        float Dgb = __fmul_rn(dgb, dgb);
        float t = __fadd_rn(__fadd_rn(__fmul_rn(Drg, Drg), __fmul_rn(Drb, Drb)),
                            __fmul_rn(Dgb, Dgb));
        out[b] = __fsqrt_rn(t);
    }
}

// ---------------------------------------------------------------------------
extern "C" void kernel_launch(void* const* d_in, const int* in_sizes, int n_in,
                              void* d_out, int out_size) {
    const float* x = (const float*)d_in[0];
    float* out = (float*)d_out;

    init_kernel<<<BB, 512>>>(x);
    for (int it = 0; it < SLIC_ITERS; it++) {
        assign_kernel<<<dim3(64, BB), 256>>>(x, 0);
        update_kernel<<<BB, 64>>>();
    }
    assign_kernel<<<dim3(64, BB), 256>>>(x, 1);       // final assign, store labels + counts
    weight_kernel<<<dim3(256, BB), 256>>>(x);
    finalize_kernel<<<1, 32>>>(out);
}

// round 10
// speedup vs baseline: 4.3588x; 3.7543x over previous
#include <cuda_runtime.h>
#include <math.h>

#define Hh 512
#define Ww 512
#define NPIX (512*512)
#define KK 50
#define BB 16
#define SLIC_ITERS 10

// scratch (static device arrays; no dynamic allocation allowed)
__device__ double        g_accum[BB][KK][6];     // [0..4]=feat sums, [5]=count
__device__ float         g_centers[BB][KK][5];
__device__ unsigned char g_labels[BB][NPIX];
__device__ double        g_colorsum[BB][3];

__device__ __forceinline__ float ratio_f() {
    return (float)(10.0 / sqrt((double)NPIX / (double)KK));
}

// ---------------------------------------------------------------------------
// init: zero accumulators + grid-initialized centers (first 50 of 8x8 grid)
// ---------------------------------------------------------------------------
__global__ void init_kernel(const float* __restrict__ x) {
    int b = blockIdx.x;
    int tid = threadIdx.x;
    if (tid < KK * 6) ((double*)g_accum[b])[tid] = 0.0;
    if (b == 0 && tid >= 448 && tid < 448 + BB * 3) ((double*)g_colorsum)[tid - 448] = 0.0;
    if (tid < KK) {
        int i = tid >> 3, j = tid & 7;
        int y = 32 + 64 * i;
        int xc = 32 + 64 * j;
        const float* xb = x + (size_t)b * 3 * NPIX;
        float r  = xb[y * Ww + xc];
        float g  = xb[NPIX + y * Ww + xc];
        float bl = xb[2 * NPIX + y * Ww + xc];
        float fr = ratio_f();
        g_centers[b][tid][0] = r;
        g_centers[b][tid][1] = g;
        g_centers[b][tid][2] = bl;
        g_centers[b][tid][3] = __fmul_rn((float)y, fr);
        g_centers[b][tid][4] = __fmul_rn((float)xc, fr);
    }
}

// ---------------------------------------------------------------------------
// assign + accumulate segment sums.
// Block = 64x64 pixel tile; 1 thread = 4x4 pixel patch (16x16 patches).
// Exact spatial pruning (labels bit-identical): candidate iff
//   spatialMin2_j <= min_j'(spatialMax2_j') + 3 (color slack) [+ fp pad]
// Candidates compacted ascending-j; +INF sentinel padding; fixed 16-candidate
// unrolled rounds.  d_j = ||c_j||^2 - 2 f.c_j  (f^2 dropped, argmin-safe)
//
// Accumulation (R9): WARP-AGGREGATED. Warp computes present-label mask, each
// lane forms predicated fp32 partials per label, shfl-tree reduces, and ONLY
// lane 0 issues the global f64 atomicAdd. This removes the 32-lane
// same-address REDG serialization at L2 that dominated R5-R8 (3.8M -> 0.25M
// atomic lane-ops per pass).
// ---------------------------------------------------------------------------
__global__ __launch_bounds__(256) void assign_kernel(const float* __restrict__ x,
                                                     int storeLabels) {
    __shared__ float4 s_candA[64];            // {-2c0,-2c1,-2c2,-2c3}
    __shared__ float2 s_candB[64];            // {-2c4, ||c||^2 or +INF sentinel}
    __shared__ unsigned char s_jidx[64];
    __shared__ float s_smax[64];
    __shared__ unsigned int s_mask[2];
    __shared__ float s_T;

    int b   = blockIdx.y;
    int tid = threadIdx.x;
    int tileX = (blockIdx.x & 7) << 6;
    int tileY = (blockIdx.x >> 3) << 6;

    float fr = ratio_f();
    float byLo = __fmul_rn((float)tileY, fr);
    float byHi = __fmul_rn((float)(tileY + 63), fr);
    float bxLo = __fmul_rn((float)tileX, fr);
    float bxHi = __fmul_rn((float)(tileX + 63), fr);

    float c0 = 0.f, c1 = 0.f, c2 = 0.f, c3 = 0.f, c4 = 0.f, smin = 0.f;
    if (tid < 64) {
        s_candA[tid] = make_float4(0.f, 0.f, 0.f, 0.f);
        s_candB[tid] = make_float2(0.f, __int_as_float(0x7f800000));  // +INF
        s_jidx[tid] = 0;
        s_smax[tid] = 3.4e38f;
    }
    if (tid < KK) {
        c0 = g_centers[b][tid][0];
        c1 = g_centers[b][tid][1];
        c2 = g_centers[b][tid][2];
        c3 = g_centers[b][tid][3];
        c4 = g_centers[b][tid][4];
        float dyo = fmaxf(fmaxf(byLo - c3, c3 - byHi), 0.0f);
        float dxo = fmaxf(fmaxf(bxLo - c4, c4 - bxHi), 0.0f);
        smin = dyo * dyo + dxo * dxo;
        float dyM = fmaxf(fabsf(c3 - byLo), fabsf(c3 - byHi));
        float dxM = fmaxf(fabsf(c4 - bxLo), fabsf(c4 - bxHi));
        s_smax[tid] = dyM * dyM + dxM * dxM;
    }
    __syncthreads();
    if (tid < 32) {                        // warp-parallel min reduction
        float v = fminf(s_smax[tid], s_smax[tid + 32]);
#pragma unroll
        for (int off = 16; off > 0; off >>= 1)
            v = fminf(v, __shfl_xor_sync(0xffffffffu, v, off));
        if (tid == 0) s_T = v + 3.0f + 1e-3f;  // color slack + fp pad
    }
    __syncthreads();
    bool keep = (tid < KK) && (smin <= s_T);
    unsigned int wm = __ballot_sync(0xffffffffu, keep);
    if (tid < 64 && (tid & 31) == 0) s_mask[tid >> 5] = wm;
    __syncthreads();
    unsigned int m0 = s_mask[0], m1 = s_mask[1];
    if (keep) {
        unsigned int mm = (tid < 32) ? m0 : m1;
        int base = (tid < 32) ? 0 : __popc(m0);
        int pos = base + __popc(mm & ((1u << (tid & 31)) - 1u));
        float cc = __fmul_rn(c0, c0);
        cc = __fmaf_rn(c1, c1, cc);
        cc = __fmaf_rn(c2, c2, cc);
        cc = __fmaf_rn(c3, c3, cc);
        cc = __fmaf_rn(c4, c4, cc);
        s_candA[pos] = make_float4(__fmul_rn(-2.0f, c0), __fmul_rn(-2.0f, c1),
                                   __fmul_rn(-2.0f, c2), __fmul_rn(-2.0f, c3));
        s_candB[pos] = make_float2(__fmul_rn(-2.0f, c4), cc);
        s_jidx[pos] = (unsigned char)tid;
    }
    int C = __popc(m0) + __popc(m1);
    __syncthreads();

    int y0 = tileY + ((tid >> 4) << 2);
    int x0 = tileX + ((tid & 15) << 2);

    const float* xr = x + (size_t)b * 3 * NPIX;
    const float* xg = xr + NPIX;
    const float* xb = xr + 2 * NPIX;

    float fxc[4], fy[4];
#pragma unroll
    for (int i = 0; i < 4; i++) fxc[i] = __fmul_rn((float)(x0 + i), fr);
#pragma unroll
    for (int i = 0; i < 4; i++) fy[i] = __fmul_rn((float)(y0 + i), fr);

    // load the full 4x4 patch (3 channels)
    float4 Rr[4], Gr[4], Br[4];
#pragma unroll
    for (int r = 0; r < 4; r++) {
        Rr[r] = *(const float4*)(xr + (y0 + r) * Ww + x0);
        Gr[r] = *(const float4*)(xg + (y0 + r) * Ww + x0);
        Br[r] = *(const float4*)(xb + (y0 + r) * Ww + x0);
    }

    float dmin[16];
    int   lab[16];
#pragma unroll
    for (int p = 0; p < 16; p++) { dmin[p] = 3.4e38f; lab[p] = 0; }

    // fixed-trip unrolled rounds of 16 candidates (sentinel-padded, exact)
    int rounds = (C + 15) >> 4;            // 1 typically
    for (int rd = 0; rd < rounds; rd++) {
        int cbase = rd << 4;
#pragma unroll
        for (int i = 0; i < 16; i++) {
            int c = cbase + i;
            float4 cA = s_candA[c];
            float2 cB = s_candB[c];
            float e0 = __fmaf_rn(cA.w, fy[0], cB.y);
            float e1 = __fmaf_rn(cA.w, fy[1], cB.y);
            float e2 = __fmaf_rn(cA.w, fy[2], cB.y);
            float e3 = __fmaf_rn(cA.w, fy[3], cB.y);
#pragma unroll
            for (int r = 0; r < 4; r++) {
                float er = (r == 0) ? e0 : (r == 1) ? e1 : (r == 2) ? e2 : e3;
                const float* Rp = (const float*)&Rr[r];
                const float* Gp = (const float*)&Gr[r];
                const float* Bp = (const float*)&Br[r];
#pragma unroll
                for (int q = 0; q < 4; q++) {
                    float d = __fmaf_rn(cB.x, fxc[q], er);
                    d = __fmaf_rn(cA.x, Rp[q], d);
                    d = __fmaf_rn(cA.y, Gp[q], d);
                    d = __fmaf_rn(cA.z, Bp[q], d);
                    int p = r * 4 + q;
                    if (d < dmin[p]) { dmin[p] = d; lab[p] = c; }
                }
            }
        }
    }

    if (storeLabels) {
#pragma unroll
        for (int r = 0; r < 4; r++) {
            uchar4 L4 = make_uchar4(s_jidx[lab[r * 4 + 0]], s_jidx[lab[r * 4 + 1]],
                                    s_jidx[lab[r * 4 + 2]], s_jidx[lab[r * 4 + 3]]);
            *(uchar4*)&g_labels[b][(y0 + r) * Ww + x0] = L4;
        }
    }

    // ---- warp-aggregated reduction ----
    // present-slot mask for this thread (slots are 0..63)
    unsigned int pmLo = 0, pmHi = 0;
#pragma unroll
    for (int p = 0; p < 16; p++) {
        int l = lab[p];
        if (l < 32) pmLo |= (1u << l);
        else        pmHi |= (1u << (l - 32));
    }
    // warp-wide OR
    pmLo = __reduce_or_sync(0xffffffffu, pmLo);
    pmHi = __reduce_or_sync(0xffffffffu, pmHi);

    double* gacc = (double*)g_accum[b];
    int lane = tid & 31;

#pragma unroll 1
    for (int half = 0; half < 2; half++) {
        unsigned int m = (half == 0) ? pmLo : pmHi;
        int cofs = (half == 0) ? 0 : 32;
        while (m) {
            int c = __ffs(m) - 1;
            m &= (m - 1u);
            int slot = c + cofs;
            // predicated per-thread partials (fp32, bounded)
            float cnt = 0.f, sR = 0.f, sG = 0.f, sB = 0.f, sY = 0.f, sX = 0.f;
#pragma unroll
            for (int p = 0; p < 16; p++) {
                float mm = (lab[p] == slot) ? 1.0f : 0.0f;
                int r = p >> 2, q = p & 3;
                cnt += mm;
                sR = __fmaf_rn(mm, ((const float*)&Rr[r])[q], sR);
                sG = __fmaf_rn(mm, ((const float*)&Gr[r])[q], sG);
                sB = __fmaf_rn(mm, ((const float*)&Br[r])[q], sB);
                sY = __fmaf_rn(mm, fy[r], sY);
                sX = __fmaf_rn(mm, fxc[q], sX);
            }
            // warp tree-reduce (deterministic)
#pragma unroll
            for (int off = 16; off > 0; off >>= 1) {
                cnt += __shfl_xor_sync(0xffffffffu, cnt, off);
                sR  += __shfl_xor_sync(0xffffffffu, sR, off);
                sG  += __shfl_xor_sync(0xffffffffu, sG, off);
                sB  += __shfl_xor_sync(0xffffffffu, sB, off);
                sY  += __shfl_xor_sync(0xffffffffu, sY, off);
                sX  += __shfl_xor_sync(0xffffffffu, sX, off);
            }
            if (lane == 0 && cnt != 0.f) {
                int jj = s_jidx[slot];
                atomicAdd(&gacc[jj * 6 + 0], (double)sR);
                atomicAdd(&gacc[jj * 6 + 1], (double)sG);
                atomicAdd(&gacc[jj * 6 + 2], (double)sB);
                atomicAdd(&gacc[jj * 6 + 3], (double)sY);
                atomicAdd(&gacc[jj * 6 + 4], (double)sX);
                atomicAdd(&gacc[jj * 6 + 5], (double)cnt);
            }
        }
    }
}

// ---------------------------------------------------------------------------
// centers <- sums / max(cnt,1); zero accumulator for next pass
// ---------------------------------------------------------------------------
__global__ void update_kernel() {
    int b = blockIdx.x;
    int k = threadIdx.x;
    if (k < KK) {
        double* a = g_accum[b][k];
        double cnt = a[5];
        double dv = cnt > 1.0 ? cnt : 1.0;
#pragma unroll
        for (int c = 0; c < 5; c++) {
            g_centers[b][k][c] = (float)(a[c] / dv);
            a[c] = 0.0;
        }
        a[5] = 0.0;
    }
}

// ---------------------------------------------------------------------------
// weighted color sum: w = 1/max(cnt,1) (fp32, like JAX); per-thread fp32
// partial (4 products), widened to double in the warp reduction + atomic
// ---------------------------------------------------------------------------
__global__ __launch_bounds__(256) void weight_kernel(const float* __restrict__ x) {
    __shared__ float s_inv[KK];
    int b   = blockIdx.y;
    int tid = threadIdx.x;
    if (tid < KK) {
        float cnt = (float)g_accum[b][tid][5];
        cnt = fmaxf(cnt, 1.0f);
        s_inv[tid] = __fdiv_rn(1.0f, cnt);
    }
    __syncthreads();

    int idx = (blockIdx.x * 256 + tid) * 4;
    const float* xr = x + (size_t)b * 3 * NPIX;
    const float* xg = xr + NPIX;
    const float* xb = xr + 2 * NPIX;
    float4 R  = *(const float4*)(xr + idx);
    float4 G  = *(const float4*)(xg + idx);
    float4 Bc = *(const float4*)(xb + idx);
    uchar4 L  = *(const uchar4*)&g_labels[b][idx];

    float w0 = s_inv[L.x], w1 = s_inv[L.y], w2 = s_inv[L.z], w3 = s_inv[L.w];
    float frt = __fadd_rn(__fadd_rn(__fmul_rn(R.x, w0), __fmul_rn(R.y, w1)),
                          __fadd_rn(__fmul_rn(R.z, w2), __fmul_rn(R.w, w3)));
    float fgt = __fadd_rn(__fadd_rn(__fmul_rn(G.x, w0), __fmul_rn(G.y, w1)),
                          __fadd_rn(__fmul_rn(G.z, w2), __fmul_rn(G.w, w3)));
    float fbt = __fadd_rn(__fadd_rn(__fmul_rn(Bc.x, w0), __fmul_rn(Bc.y, w1)),
                          __fadd_rn(__fmul_rn(Bc.z, w2), __fmul_rn(Bc.w, w3)));
    double sr = (double)frt, sg = (double)fgt, sb = (double)fbt;
#pragma unroll
    for (int off = 16; off > 0; off >>= 1) {
        sr += __shfl_down_sync(0xffffffffu, sr, off);
        sg += __shfl_down_sync(0xffffffffu, sg, off);
        sb += __shfl_down_sync(0xffffffffu, sb, off);
    }
    if ((tid & 31) == 0) {
        atomicAdd(&g_colorsum[b][0], sr);
        atomicAdd(&g_colorsum[b][1], sg);
        atomicAdd(&g_colorsum[b][2], sb);
    }
}

// ---------------------------------------------------------------------------
// finalize: fp32 epilogue mirroring the reference formula
// ---------------------------------------------------------------------------
__global__ void finalize_kernel(float* __restrict__ out) {
    int b = threadIdx.x;
    if (b < BB) {
        float mr = (float)(g_colorsum[b][0] / (double)NPIX);
        float mg = (float)(g_colorsum[b][1] / (double)NPIX);
        float mb = (float)(g_colorsum[b][2] / (double)NPIX);
        float drg = __fadd_rn(mr, -mg);
        float drb = __fadd_rn(mr, -mb);
        float dgb = __fadd_rn(mb, -mg);
        float Drg = __fmul_rn(drg, drg);
        float Drb = __fmul_rn(drb, drb);
        float Dgb = __fmul_rn(dgb, dgb);
        float t = __fadd_rn(__fadd_rn(__fmul_rn(Drg, Drg), __fmul_rn(Drb, Drb)),
                            __fmul_rn(Dgb, Dgb));
        out[b] = __fsqrt_rn(t);
    }
}

// ---------------------------------------------------------------------------
extern "C" void kernel_launch(void* const* d_in, const int* in_sizes, int n_in,
                              void* d_out, int out_size) {
    const float* x = (const float*)d_in[0];
    float* out = (float*)d_out;

    init_kernel<<<BB, 512>>>(x);
    for (int it = 0; it < SLIC_ITERS; it++) {
        assign_kernel<<<dim3(64, BB), 256>>>(x, 0);
        update_kernel<<<BB, 64>>>();
    }
    assign_kernel<<<dim3(64, BB), 256>>>(x, 1);       // final assign, store labels + counts
    weight_kernel<<<dim3(256, BB), 256>>>(x);
    finalize_kernel<<<1, 32>>>(out);
}